// round 1
// baseline (speedup 1.0000x reference)
#include <cuda_runtime.h>
#include <math.h>

// Problem constants
namespace {
constexpr int B_   = 32;
constexpr int S_   = 1024;
constexpr int D_   = 512;
constexpr int H_   = 4;
constexpr int E_   = 128;   // per-head q/k/v dim
constexpr int DH_  = 384;   // 3*E
constexpr int FFN_ = 2048;
constexpr int NKV_ = 1024;  // H * 2 * E  (packed k,v columns)
}

// Scratch (static __device__ — no allocations allowed)
__device__ float g_Pos[S_ * D_];                       // 2 MB
__device__ float g_X[(size_t)B_ * S_ * D_];            // 64 MB
__device__ float g_Wkv[D_ * NKV_];                     // 2 MB packed k|v weights
__device__ float g_bkv[NKV_];
__device__ float g_Wq[D_ * D_];                        // 1 MB packed q weights
__device__ float g_bq[D_];
__device__ float g_KV[(size_t)B_ * S_ * NKV_];         // 128 MB
__device__ float g_M[B_ * H_ * E_ * E_];               // 8 MB

// ---------------------------------------------------------------------------
// Positional encoding table (matches numpy formula exactly in structure)
// ---------------------------------------------------------------------------
__global__ void prep_pos_kernel() {
    int idx = blockIdx.x * blockDim.x + threadIdx.x;
    if (idx >= S_ * D_) return;
    int t = idx / D_;
    int i = idx % D_;
    float expn = (float)(2 * (i / 2)) / (float)D_;
    float ang  = (float)t / powf(10000.0f, expn);
    g_Pos[idx] = (i & 1) ? cosf(ang) : sinf(ang);
}

// ---------------------------------------------------------------------------
// Pack Wp (H,D,384) into Wkv (D x 1024: col = h*256 + j, j<128 -> k, else v)
// and Wq (D x 512: col = h*128 + j), plus biases.
// ---------------------------------------------------------------------------
__global__ void prep_w_kernel(const float* __restrict__ Wp,
                              const float* __restrict__ bp) {
    int idx = blockIdx.x * blockDim.x + threadIdx.x;
    if (idx < D_ * NKV_) {
        int d = idx / NKV_, c = idx % NKV_;
        int h = c >> 8, j = c & 255;
        g_Wkv[idx] = Wp[((size_t)h * D_ + d) * DH_ + 128 + j];
    }
    if (idx < D_ * D_) {
        int d = idx / D_, c = idx % D_;
        int h = c >> 7, j = c & 127;
        g_Wq[idx] = Wp[((size_t)h * D_ + d) * DH_ + j];
    }
    if (idx < NKV_) {
        int h = idx >> 8, j = idx & 255;
        g_bkv[idx] = bp[h * DH_ + 128 + j];
    }
    if (idx < D_) {
        int h = idx >> 7, j = idx & 127;
        g_bq[idx] = bp[h * DH_ + j];
    }
}

// ---------------------------------------------------------------------------
// X = emb[tokens] + pos  (vectorized float4)
// ---------------------------------------------------------------------------
__global__ void build_x_kernel(const int* __restrict__ tok,
                               const float* __restrict__ emb) {
    int idx = blockIdx.x * blockDim.x + threadIdx.x;  // over B*S*(D/4)
    if (idx >= B_ * S_ * (D_ / 4)) return;
    int row = idx >> 7;          // D/4 = 128
    int d4  = idx & 127;
    int s   = row & (S_ - 1);
    int t   = tok[row];
    float4 e = ((const float4*)emb)[(size_t)t * (D_ / 4) + d4];
    float4 p = ((const float4*)g_Pos)[s * (D_ / 4) + d4];
    float4 r;
    r.x = e.x + p.x; r.y = e.y + p.y; r.z = e.z + p.z; r.w = e.w + p.w;
    ((float4*)g_X)[idx] = r;
}

// ---------------------------------------------------------------------------
// SGEMM: KV[32768 x 1024] = X[32768 x 512] @ Wkv[512 x 1024] + bkv
// 128x128x8 block, 8x8 per thread, 256 threads.
// ---------------------------------------------------------------------------
__global__ __launch_bounds__(256) void sgemm_kv_kernel() {
    __shared__ float As[8][128];
    __shared__ float Bs[8][128];
    const int K = D_;
    int tm0 = blockIdx.y * 128;
    int tn0 = blockIdx.x * 128;
    int tid = threadIdx.x;
    int tx = tid & 15, ty = tid >> 4;
    int aRow = tid >> 1;
    int aCol = (tid & 1) * 4;
    int bRow = tid >> 5;
    int bCol = (tid & 31) * 4;

    float acc[8][8] = {};
    const float* A  = g_X + (size_t)tm0 * K;
    const float* Bw = g_Wkv + tn0;

    for (int k0 = 0; k0 < K; k0 += 8) {
        float4 av = *(const float4*)(A + (size_t)aRow * K + k0 + aCol);
        As[aCol + 0][aRow] = av.x;
        As[aCol + 1][aRow] = av.y;
        As[aCol + 2][aRow] = av.z;
        As[aCol + 3][aRow] = av.w;
        *(float4*)&Bs[bRow][bCol] =
            *(const float4*)(Bw + (size_t)(k0 + bRow) * NKV_ + bCol);
        __syncthreads();
#pragma unroll
        for (int k = 0; k < 8; k++) {
            float4 a0 = *(const float4*)&As[k][ty * 8];
            float4 a1 = *(const float4*)&As[k][ty * 8 + 4];
            float4 b0 = *(const float4*)&Bs[k][tx * 8];
            float4 b1 = *(const float4*)&Bs[k][tx * 8 + 4];
            float ra[8] = {a0.x, a0.y, a0.z, a0.w, a1.x, a1.y, a1.z, a1.w};
            float rb[8] = {b0.x, b0.y, b0.z, b0.w, b1.x, b1.y, b1.z, b1.w};
#pragma unroll
            for (int i = 0; i < 8; i++)
#pragma unroll
                for (int j = 0; j < 8; j++) acc[i][j] += ra[i] * rb[j];
        }
        __syncthreads();
    }
#pragma unroll
    for (int i = 0; i < 8; i++) {
        int row = tm0 + ty * 8 + i;
        float* C = g_KV + (size_t)row * NKV_ + tn0;
#pragma unroll
        for (int j = 0; j < 8; j += 4) {
            int col = tx * 8 + j;
            float4 v;
            v.x = acc[i][j + 0] + g_bkv[tn0 + col + 0];
            v.y = acc[i][j + 1] + g_bkv[tn0 + col + 1];
            v.z = acc[i][j + 2] + g_bkv[tn0 + col + 2];
            v.w = acc[i][j + 3] + g_bkv[tn0 + col + 3];
            *(float4*)(C + col) = v;
        }
    }
}

// ---------------------------------------------------------------------------
// Moment kernel: M[b,h] = K^T V  (128x128, reduced over S=1024)
// One block per (b,h). 256 threads, 8x8 per thread, 32-row t-tiles.
// ---------------------------------------------------------------------------
__global__ __launch_bounds__(256) void kmom_kernel() {
    __shared__ float Ks[32][128];
    __shared__ float Vs[32][128];
    int bh = blockIdx.x;
    int b = bh / H_, h = bh % H_;
    int tid = threadIdx.x;
    int tx = tid & 15, ty = tid >> 4;
    float acc[8][8] = {};
    const float* base = g_KV + (size_t)b * S_ * NKV_ + h * 256;

    for (int t0 = 0; t0 < S_; t0 += 32) {
#pragma unroll
        for (int i = 0; i < 4; i++) {
            int idx = tid + i * 256;       // 0..1023
            int row = idx >> 5;
            int c4  = (idx & 31) * 4;
            const float* p = base + (size_t)(t0 + row) * NKV_;
            *(float4*)&Ks[row][c4] = *(const float4*)(p + c4);
            *(float4*)&Vs[row][c4] = *(const float4*)(p + 128 + c4);
        }
        __syncthreads();
#pragma unroll
        for (int tt = 0; tt < 32; tt++) {
            float4 k0 = *(const float4*)&Ks[tt][ty * 8];
            float4 k1 = *(const float4*)&Ks[tt][ty * 8 + 4];
            float4 v0 = *(const float4*)&Vs[tt][tx * 8];
            float4 v1 = *(const float4*)&Vs[tt][tx * 8 + 4];
            float rk[8] = {k0.x, k0.y, k0.z, k0.w, k1.x, k1.y, k1.z, k1.w};
            float rv[8] = {v0.x, v0.y, v0.z, v0.w, v1.x, v1.y, v1.z, v1.w};
#pragma unroll
            for (int i = 0; i < 8; i++)
#pragma unroll
                for (int j = 0; j < 8; j++) acc[i][j] += rk[i] * rv[j];
        }
        __syncthreads();
    }
    float* Mp = g_M + (size_t)bh * E_ * E_;
#pragma unroll
    for (int i = 0; i < 8; i++) {
        int e = ty * 8 + i;
#pragma unroll
        for (int j = 0; j < 8; j += 4) {
            float4 v;
            v.x = acc[i][j + 0];
            v.y = acc[i][j + 1];
            v.z = acc[i][j + 2];
            v.w = acc[i][j + 3];
            *(float4*)&Mp[e * E_ + tx * 8 + j] = v;
        }
    }
}

// ---------------------------------------------------------------------------
// Per-batch epilogue: q0, heads, Wo, LN1, FFN, LN2, classifier head.
// One block per batch, 512 threads.
// ---------------------------------------------------------------------------
__device__ __forceinline__ float block_sum_512(float v, float* red) {
    int tid = threadIdx.x;
    red[tid] = v;
    __syncthreads();
#pragma unroll
    for (int s = 256; s > 0; s >>= 1) {
        if (tid < s) red[tid] += red[tid + s];
        __syncthreads();
    }
    float r = red[0];
    __syncthreads();
    return r;
}

__global__ __launch_bounds__(512) void final_kernel(
    const float* __restrict__ Wo,  const float* __restrict__ bo,
    const float* __restrict__ g1,  const float* __restrict__ bln1,
    const float* __restrict__ W1,  const float* __restrict__ b1,
    const float* __restrict__ W2,  const float* __restrict__ b2,
    const float* __restrict__ g2,  const float* __restrict__ bln2,
    const float* __restrict__ Wh,  const float* __restrict__ bh,
    const float* __restrict__ Wf,  const float* __restrict__ bf,
    float* __restrict__ out, int out_size)
{
    __shared__ float x0[D_];
    __shared__ float t1[D_];
    __shared__ float t2[D_];
    __shared__ float hbuf[FFN_];
    __shared__ float red[512];

    int b = blockIdx.x;
    int tid = threadIdx.x;

    // x at position 0
    x0[tid] = g_X[(size_t)b * S_ * D_ + tid];
    __syncthreads();

    // q0[c] = x0 . Wq[:,c] + bq
    float accq = g_bq[tid];
    for (int d = 0; d < D_; d++) accq += x0[d] * g_Wq[d * D_ + tid];
    t1[tid] = accq;
    __syncthreads();

    // heads[c] = scale * q0[h,:] . M[b,h][:,f]
    {
        int h = tid >> 7, f = tid & 127;
        const float* Mh = g_M + (size_t)(b * H_ + h) * E_ * E_;
        float acc = 0.f;
        for (int e = 0; e < E_; e++) acc += t1[h * E_ + e] * Mh[e * E_ + f];
        t2[tid] = acc * 0.03125f;  // rsqrt(1024)
    }
    __syncthreads();

    // attn + residual
    float acca = bo[tid];
    for (int c = 0; c < D_; c++) acca += t2[c] * Wo[c * D_ + tid];
    float r1 = acca + x0[tid];

    // LayerNorm 1
    float mu  = block_sum_512(r1, red) * (1.f / D_);
    float dv  = r1 - mu;
    float var = block_sum_512(dv * dv, red) * (1.f / D_);
    float xl  = dv * rsqrtf(var + 1e-3f) * g1[tid] + bln1[tid];
    t1[tid] = xl;
    __syncthreads();

    // FFN up (+ReLU): each thread 4 outputs
#pragma unroll
    for (int r = 0; r < 4; r++) {
        int f = tid + 512 * r;
        float a = b1[f];
        for (int d = 0; d < D_; d++) a += t1[d] * W1[(size_t)d * FFN_ + f];
        hbuf[f] = fmaxf(a, 0.f);
    }
    __syncthreads();

    // FFN down + residual
    float a2 = b2[tid];
    for (int f = 0; f < FFN_; f++) a2 += hbuf[f] * W2[(size_t)f * D_ + tid];
    float r2 = a2 + t1[tid];

    // LayerNorm 2
    mu  = block_sum_512(r2, red) * (1.f / D_);
    dv  = r2 - mu;
    var = block_sum_512(dv * dv, red) * (1.f / D_);
    float x2 = dv * rsqrtf(var + 1e-3f) * g2[tid] + bln2[tid];
    t2[tid] = x2;
    __syncthreads();

    // hid = relu(x2 @ Wh + bh); logit = hid . Wf + bf
    float ah = bh[tid];
    for (int e = 0; e < D_; e++) ah += t2[e] * Wh[e * D_ + tid];
    ah = fmaxf(ah, 0.f);
    float logit = block_sum_512(ah * Wf[tid], red) + bf[0];

    if (tid == 0) {
        if (b < out_size)       out[b]       = logit;
        if (B_ + b < out_size)  out[B_ + b]  = 1.f / (1.f + expf(-logit));
    }
}

// ---------------------------------------------------------------------------
extern "C" void kernel_launch(void* const* d_in, const int* in_sizes, int n_in,
                              void* d_out, int out_size) {
    const int*   inputs = (const int*)  d_in[0];
    const float* emb    = (const float*)d_in[1];
    const float* Wp     = (const float*)d_in[2];
    const float* bp     = (const float*)d_in[3];
    const float* Wo     = (const float*)d_in[4];
    const float* bo     = (const float*)d_in[5];
    const float* ln1g   = (const float*)d_in[6];
    const float* ln1b   = (const float*)d_in[7];
    const float* W1     = (const float*)d_in[8];
    const float* b1     = (const float*)d_in[9];
    const float* W2     = (const float*)d_in[10];
    const float* b2     = (const float*)d_in[11];
    const float* ln2g   = (const float*)d_in[12];
    const float* ln2b   = (const float*)d_in[13];
    const float* Wh     = (const float*)d_in[14];
    const float* bhp    = (const float*)d_in[15];
    const float* Wf     = (const float*)d_in[16];
    const float* bf     = (const float*)d_in[17];
    float* out = (float*)d_out;

    prep_pos_kernel<<<(S_ * D_ + 255) / 256, 256>>>();
    prep_w_kernel<<<(D_ * NKV_ + 255) / 256, 256>>>(Wp, bp);
    build_x_kernel<<<(B_ * S_ * (D_ / 4) + 255) / 256, 256>>>(inputs, emb);
    sgemm_kv_kernel<<<dim3(NKV_ / 128, (B_ * S_) / 128), 256>>>();
    kmom_kernel<<<B_ * H_, 256>>>();
    final_kernel<<<B_, 512>>>(Wo, bo, ln1g, ln1b, W1, b1, W2, b2,
                              ln2g, ln2b, Wh, bhp, Wf, bf, out, out_size);
}

// round 2
// speedup vs baseline: 2.5376x; 2.5376x over previous
#include <cuda_runtime.h>
#include <math.h>

namespace {
constexpr int B_   = 32;
constexpr int S_   = 1024;
constexpr int D_   = 512;
constexpr int H_   = 4;
constexpr int E_   = 128;
constexpr int DH_  = 384;   // 3*E
constexpr int FFN_ = 2048;
constexpr int NCHUNK_ = 8;  // t-chunks per batch in alpha_y pass
}

// Static scratch
__device__ float g_Pos[S_ * D_];                          // 2 MB
__device__ float g_X[(size_t)B_ * S_ * D_];               // 64 MB
__device__ float g_w[B_ * H_ * D_];                       // 256 KB  (w_h per batch)
__device__ float g_c[B_ * H_];
__device__ float g_ypart[B_ * NCHUNK_ * H_ * D_];         // 2 MB
__device__ float g_Apart[B_ * NCHUNK_ * H_];

// ---------------------------------------------------------------------------
// Positional encoding table
// ---------------------------------------------------------------------------
__global__ void prep_pos_kernel() {
    int idx = blockIdx.x * blockDim.x + threadIdx.x;
    if (idx >= S_ * D_) return;
    int t = idx / D_;
    int i = idx % D_;
    float expn = (float)(2 * (i / 2)) / (float)D_;
    float ang  = (float)t / powf(10000.0f, expn);
    g_Pos[idx] = (i & 1) ? cosf(ang) : sinf(ang);
}

// ---------------------------------------------------------------------------
// X = emb[tokens] + pos   (float4)
// ---------------------------------------------------------------------------
__global__ void build_x_kernel(const int* __restrict__ tok,
                               const float* __restrict__ emb) {
    int idx = blockIdx.x * blockDim.x + threadIdx.x;
    if (idx >= B_ * S_ * (D_ / 4)) return;
    int row = idx >> 7;
    int d4  = idx & 127;
    int s   = row & (S_ - 1);
    int t   = tok[row];
    float4 e = ((const float4*)emb)[(size_t)t * (D_ / 4) + d4];
    float4 p = ((const float4*)g_Pos)[s * (D_ / 4) + d4];
    float4 r;
    r.x = e.x + p.x; r.y = e.y + p.y; r.z = e.z + p.z; r.w = e.w + p.w;
    ((float4*)g_X)[idx] = r;
}

// ---------------------------------------------------------------------------
// Per batch: q0_h = Wq_hT x0 + bq_h ;  w_h = Wk_h q0_h ;  c_h = q0_h . bk_h
// Wp layout: (H, D, 384): q cols [0,128), k cols [128,256), v cols [256,384)
// Grid: B blocks, 512 threads.
// ---------------------------------------------------------------------------
__global__ __launch_bounds__(512) void qw_kernel(
    const float* __restrict__ Wp, const float* __restrict__ bp)
{
    __shared__ float x0s[D_];
    __shared__ float q0s[D_];   // [h*128 + e]
    int b = blockIdx.x;
    int tid = threadIdx.x;

    x0s[tid] = g_X[(size_t)b * S_ * D_ + tid];
    __syncthreads();

    // q0
    {
        int h = tid >> 7, e = tid & 127;
        float acc = bp[h * DH_ + e];
        const float* wp = Wp + (size_t)h * D_ * DH_ + e;
#pragma unroll 8
        for (int d = 0; d < D_; d++) acc += x0s[d] * wp[(size_t)d * DH_];
        q0s[tid] = acc;
    }
    __syncthreads();

    // c_h
    if (tid < H_) {
        float c = 0.f;
        for (int e = 0; e < E_; e++) c += q0s[tid * E_ + e] * bp[tid * DH_ + 128 + e];
        g_c[b * H_ + tid] = c;
    }

    // w_h[d] = sum_e Wp[h,d,128+e] * q0_h[e]   (4 outputs per thread)
#pragma unroll
    for (int r = 0; r < 4; r++) {
        int idx = tid + 512 * r;            // h*512 + d
        int h = idx >> 9, d = idx & 511;
        const float4* wp4 = (const float4*)(Wp + ((size_t)h * D_ + d) * DH_ + 128);
        const float4* q4  = (const float4*)(q0s + h * E_);
        float acc = 0.f;
#pragma unroll
        for (int e4 = 0; e4 < E_ / 4; e4++) {
            float4 wv = wp4[e4];
            float4 qv = q4[e4];
            acc += wv.x * qv.x + wv.y * qv.y + wv.z * qv.z + wv.w * qv.w;
        }
        g_w[b * (H_ * D_) + idx] = acc;
    }
}

// ---------------------------------------------------------------------------
// alpha/y pass: per (chunk, b): 128 t-rows.
//  phase1: alpha[t][h] = w_h . x_t + c_h        (warp per t)
//  phase2: ypart[h][d] = sum_t alpha[t][h] x_t[d];  Apart[h] = sum_t alpha[t][h]
// Grid: (NCHUNK_, B_), 256 threads.
// ---------------------------------------------------------------------------
__global__ __launch_bounds__(256) void alpha_y_kernel() {
    __shared__ float ws[H_ * D_];      // 8 KB
    __shared__ float alpha[128][H_];
    __shared__ float cs[H_];

    int chunk = blockIdx.x, b = blockIdx.y;
    int tid = threadIdx.x;
    int lane = tid & 31, wid = tid >> 5;
    int tbase = chunk * 128;

    // load w, c
#pragma unroll
    for (int r = 0; r < 8; r++) ws[tid + 256 * r] = g_w[b * (H_ * D_) + tid + 256 * r];
    if (tid < H_) cs[tid] = g_c[b * H_ + tid];
    __syncthreads();

    const float4* ws4 = (const float4*)ws;

    // phase 1: each warp handles 16 t-rows
    for (int j = 0; j < 16; j++) {
        int t = wid * 16 + j;
        const float4* xr = (const float4*)(g_X + ((size_t)b * S_ + tbase + t) * D_);
        float s0 = 0.f, s1 = 0.f, s2 = 0.f, s3 = 0.f;
#pragma unroll
        for (int k = 0; k < 4; k++) {
            int f4 = lane + 32 * k;            // float4 index 0..127 within row
            float4 xv = xr[f4];
            float4 w0 = ws4[0 * 128 + f4];
            float4 w1 = ws4[1 * 128 + f4];
            float4 w2 = ws4[2 * 128 + f4];
            float4 w3 = ws4[3 * 128 + f4];
            s0 += xv.x * w0.x + xv.y * w0.y + xv.z * w0.z + xv.w * w0.w;
            s1 += xv.x * w1.x + xv.y * w1.y + xv.z * w1.z + xv.w * w1.w;
            s2 += xv.x * w2.x + xv.y * w2.y + xv.z * w2.z + xv.w * w2.w;
            s3 += xv.x * w3.x + xv.y * w3.y + xv.z * w3.z + xv.w * w3.w;
        }
#pragma unroll
        for (int off = 16; off > 0; off >>= 1) {
            s0 += __shfl_xor_sync(0xffffffff, s0, off);
            s1 += __shfl_xor_sync(0xffffffff, s1, off);
            s2 += __shfl_xor_sync(0xffffffff, s2, off);
            s3 += __shfl_xor_sync(0xffffffff, s3, off);
        }
        if (lane == 0) {
            alpha[t][0] = s0 + cs[0];
            alpha[t][1] = s1 + cs[1];
            alpha[t][2] = s2 + cs[2];
            alpha[t][3] = s3 + cs[3];
        }
    }
    __syncthreads();

    // phase 2: thread handles 2 d columns, all 4 heads
    {
        int d0 = tid * 2;
        float y00 = 0, y01 = 0, y10 = 0, y11 = 0, y20 = 0, y21 = 0, y30 = 0, y31 = 0;
        const float* Xb = g_X + ((size_t)b * S_ + tbase) * D_;
        for (int t = 0; t < 128; t++) {
            float2 xv = *(const float2*)(Xb + (size_t)t * D_ + d0);
            float a0 = alpha[t][0], a1 = alpha[t][1], a2 = alpha[t][2], a3 = alpha[t][3];
            y00 += a0 * xv.x; y01 += a0 * xv.y;
            y10 += a1 * xv.x; y11 += a1 * xv.y;
            y20 += a2 * xv.x; y21 += a2 * xv.y;
            y30 += a3 * xv.x; y31 += a3 * xv.y;
        }
        float* yp = g_ypart + ((size_t)(b * NCHUNK_ + chunk)) * (H_ * D_);
        yp[0 * D_ + d0] = y00; yp[0 * D_ + d0 + 1] = y01;
        yp[1 * D_ + d0] = y10; yp[1 * D_ + d0 + 1] = y11;
        yp[2 * D_ + d0] = y20; yp[2 * D_ + d0 + 1] = y21;
        yp[3 * D_ + d0] = y30; yp[3 * D_ + d0 + 1] = y31;
    }

    if (tid < H_) {
        float a = 0.f;
        for (int t = 0; t < 128; t++) a += alpha[t][tid];
        g_Apart[(b * NCHUNK_ + chunk) * H_ + tid] = a;
    }
}

// ---------------------------------------------------------------------------
// Final per-batch epilogue. Grid: B blocks, 512 threads.
// ---------------------------------------------------------------------------
__device__ __forceinline__ float block_sum_512(float v, float* red) {
    int tid = threadIdx.x;
    red[tid] = v;
    __syncthreads();
#pragma unroll
    for (int s = 256; s > 0; s >>= 1) {
        if (tid < s) red[tid] += red[tid + s];
        __syncthreads();
    }
    float r = red[0];
    __syncthreads();
    return r;
}

__global__ __launch_bounds__(512) void final_kernel(
    const float* __restrict__ Wp,  const float* __restrict__ bp,
    const float* __restrict__ Wo,  const float* __restrict__ bo,
    const float* __restrict__ g1,  const float* __restrict__ bln1,
    const float* __restrict__ W1,  const float* __restrict__ b1,
    const float* __restrict__ W2,  const float* __restrict__ b2,
    const float* __restrict__ g2,  const float* __restrict__ bln2,
    const float* __restrict__ Wh,  const float* __restrict__ bh,
    const float* __restrict__ Wf,  const float* __restrict__ bf,
    float* __restrict__ out, int out_size)
{
    __shared__ float x0[D_];
    __shared__ float t1[D_];
    __shared__ float t2[D_];
    __shared__ float ys[H_ * D_];
    __shared__ float As[H_];
    __shared__ float hbuf[FFN_];
    __shared__ float red[512];

    int b = blockIdx.x;
    int tid = threadIdx.x;

    x0[tid] = g_X[(size_t)b * S_ * D_ + tid];

    // reduce y partials
#pragma unroll
    for (int r = 0; r < 4; r++) {
        int i = tid + 512 * r;
        float acc = 0.f;
#pragma unroll
        for (int c = 0; c < NCHUNK_; c++)
            acc += g_ypart[((size_t)(b * NCHUNK_ + c)) * (H_ * D_) + i];
        ys[i] = acc;
    }
    if (tid < H_) {
        float a = 0.f;
        for (int c = 0; c < NCHUNK_; c++) a += g_Apart[(b * NCHUNK_ + c) * H_ + tid];
        As[tid] = a;
    }
    __syncthreads();

    // heads[h*128+f] = scale * ( sum_d ys[h][d]*Wp[h,d,256+f] + A_h*bv_h[f] )
    {
        int h = tid >> 7, f = tid & 127;
        const float* wp = Wp + (size_t)h * D_ * DH_ + 256 + f;
        const float* yh = ys + h * D_;
        float acc = As[h] * bp[h * DH_ + 256 + f];
#pragma unroll 8
        for (int d = 0; d < D_; d++) acc += yh[d] * wp[(size_t)d * DH_];
        t2[tid] = acc * 0.03125f;   // rsqrt(1024)
    }
    __syncthreads();

    // attn out + residual
    float acca = bo[tid];
#pragma unroll 8
    for (int c = 0; c < D_; c++) acca += t2[c] * Wo[(size_t)c * D_ + tid];
    float r1 = acca + x0[tid];

    // LayerNorm 1
    float mu  = block_sum_512(r1, red) * (1.f / D_);
    float dv  = r1 - mu;
    float var = block_sum_512(dv * dv, red) * (1.f / D_);
    float xl  = dv * rsqrtf(var + 1e-3f) * g1[tid] + bln1[tid];
    t1[tid] = xl;
    __syncthreads();

    // FFN up (+ReLU)
#pragma unroll
    for (int r = 0; r < 4; r++) {
        int f = tid + 512 * r;
        float a = b1[f];
#pragma unroll 8
        for (int d = 0; d < D_; d++) a += t1[d] * W1[(size_t)d * FFN_ + f];
        hbuf[f] = fmaxf(a, 0.f);
    }
    __syncthreads();

    // FFN down + residual
    float a2 = b2[tid];
#pragma unroll 8
    for (int f = 0; f < FFN_; f++) a2 += hbuf[f] * W2[(size_t)f * D_ + tid];
    float r2 = a2 + t1[tid];

    // LayerNorm 2
    mu  = block_sum_512(r2, red) * (1.f / D_);
    dv  = r2 - mu;
    var = block_sum_512(dv * dv, red) * (1.f / D_);
    float x2 = dv * rsqrtf(var + 1e-3f) * g2[tid] + bln2[tid];
    t2[tid] = x2;
    __syncthreads();

    // classifier head
    float ah = bh[tid];
#pragma unroll 8
    for (int e = 0; e < D_; e++) ah += t2[e] * Wh[(size_t)e * D_ + tid];
    ah = fmaxf(ah, 0.f);
    float logit = block_sum_512(ah * Wf[tid], red) + bf[0];

    if (tid == 0) {
        if (b < out_size)       out[b]       = logit;
        if (B_ + b < out_size)  out[B_ + b]  = 1.f / (1.f + expf(-logit));
    }
}

// ---------------------------------------------------------------------------
extern "C" void kernel_launch(void* const* d_in, const int* in_sizes, int n_in,
                              void* d_out, int out_size) {
    const int*   inputs = (const int*)  d_in[0];
    const float* emb    = (const float*)d_in[1];
    const float* Wp     = (const float*)d_in[2];
    const float* bp     = (const float*)d_in[3];
    const float* Wo     = (const float*)d_in[4];
    const float* bo     = (const float*)d_in[5];
    const float* ln1g   = (const float*)d_in[6];
    const float* ln1b   = (const float*)d_in[7];
    const float* W1     = (const float*)d_in[8];
    const float* b1     = (const float*)d_in[9];
    const float* W2     = (const float*)d_in[10];
    const float* b2     = (const float*)d_in[11];
    const float* ln2g   = (const float*)d_in[12];
    const float* ln2b   = (const float*)d_in[13];
    const float* Wh     = (const float*)d_in[14];
    const float* bhp    = (const float*)d_in[15];
    const float* Wf     = (const float*)d_in[16];
    const float* bf     = (const float*)d_in[17];
    float* out = (float*)d_out;

    prep_pos_kernel<<<(S_ * D_ + 255) / 256, 256>>>();
    build_x_kernel<<<(B_ * S_ * (D_ / 4) + 255) / 256, 256>>>(inputs, emb);
    qw_kernel<<<B_, 512>>>(Wp, bp);
    alpha_y_kernel<<<dim3(NCHUNK_, B_), 256>>>();
    final_kernel<<<B_, 512>>>(Wp, bp, Wo, bo, ln1g, ln1b, W1, b1, W2, b2,
                              ln2g, ln2b, Wh, bhp, Wf, bf, out, out_size);
}

// round 3
// speedup vs baseline: 7.1401x; 2.8137x over previous
#include <cuda_runtime.h>
#include <math.h>

namespace {
constexpr int B_   = 32;
constexpr int S_   = 1024;
constexpr int D_   = 512;
constexpr int H_   = 4;
constexpr int E_   = 128;
constexpr int DH_  = 384;
constexpr int FFN_ = 2048;
constexpr int NCHUNK_ = 8;
}

// ---------------- static scratch ----------------
__device__ float g_Pos[S_ * D_];                     // 2 MB
__device__ float g_x0[B_ * D_];
__device__ float g_w[B_ * H_ * D_];
__device__ float g_c[B_ * H_];
__device__ float g_ypart[B_ * NCHUNK_ * H_ * D_];
__device__ float g_Apart[B_ * NCHUNK_ * H_];
__device__ float g_y[B_ * H_ * D_];
__device__ float g_A[B_ * H_];
__device__ float g_hp[2][B_ * D_];      // F1 partials (heads)
__device__ float g_x1p[2][B_ * D_];     // F2 partials (attn+res, pre-LN1)
__device__ float g_x1n[B_ * D_];        // post-LN1
__device__ float g_h1p[2][B_ * FFN_];   // F3 partials (FFN up, pre-relu)
__device__ float g_x2p[8][B_ * D_];     // F4 partials (pre-LN2)
__device__ float g_x2[B_ * D_];         // post-LN2
__device__ float g_hidp[2][B_ * D_];    // F5 partials (pre-relu)

// ---------------------------------------------------------------------------
// Positional encoding table
// ---------------------------------------------------------------------------
__global__ void prep_pos_kernel() {
    int idx = blockIdx.x * blockDim.x + threadIdx.x;
    if (idx >= S_ * D_) return;
    int t = idx / D_;
    int i = idx % D_;
    float expn = (float)(2 * (i / 2)) / (float)D_;
    float ang  = (float)t / powf(10000.0f, expn);
    g_Pos[idx] = (i & 1) ? cosf(ang) : sinf(ang);
}

// ---------------------------------------------------------------------------
// Per batch: x0, q0, w_h = Wk_h q0_h, c_h = q0_h . bk_h
// ---------------------------------------------------------------------------
__global__ __launch_bounds__(512) void qw_kernel(
    const int* __restrict__ tok, const float* __restrict__ emb,
    const float* __restrict__ Wp, const float* __restrict__ bp)
{
    __shared__ float x0s[D_];
    __shared__ float q0s[D_];
    int b = blockIdx.x;
    int tid = threadIdx.x;

    {
        int t0 = tok[b * S_];
        float v = emb[(size_t)t0 * D_ + tid] + g_Pos[tid];
        x0s[tid] = v;
        g_x0[b * D_ + tid] = v;
    }
    __syncthreads();

    {   // q0[h,e]
        int h = tid >> 7, e = tid & 127;
        float acc = bp[h * DH_ + e];
        const float* wp = Wp + (size_t)h * D_ * DH_ + e;
#pragma unroll 8
        for (int d = 0; d < D_; d++) acc += x0s[d] * wp[(size_t)d * DH_];
        q0s[tid] = acc;
    }
    __syncthreads();

    if (tid < H_) {
        float c = 0.f;
        for (int e = 0; e < E_; e++) c += q0s[tid * E_ + e] * bp[tid * DH_ + 128 + e];
        g_c[b * H_ + tid] = c;
    }

#pragma unroll
    for (int r = 0; r < 4; r++) {
        int idx = tid + 512 * r;            // h*512 + d
        int h = idx >> 9, d = idx & 511;
        const float4* wp4 = (const float4*)(Wp + ((size_t)h * D_ + d) * DH_ + 128);
        const float4* q4  = (const float4*)(q0s + h * E_);
        float acc = 0.f;
#pragma unroll
        for (int e4 = 0; e4 < E_ / 4; e4++) {
            float4 wv = wp4[e4];
            float4 qv = q4[e4];
            acc += wv.x * qv.x + wv.y * qv.y + wv.z * qv.z + wv.w * qv.w;
        }
        g_w[b * (H_ * D_) + idx] = acc;
    }
}

// ---------------------------------------------------------------------------
// Fused gather + alpha + y pass (X never materialized).
// Grid (NCHUNK_, B_), 256 threads. Subtiles of 16 t-rows in shared.
// ---------------------------------------------------------------------------
__global__ __launch_bounds__(256) void alpha_y_kernel(
    const int* __restrict__ tok, const float* __restrict__ emb)
{
    __shared__ float xs[16][512];      // 32 KB
    __shared__ float al[128][4];
    __shared__ float ws[H_ * D_];      // 8 KB
    __shared__ float cs[H_];

    int chunk = blockIdx.x, b = blockIdx.y;
    int tid = threadIdx.x;
    int lane = tid & 31, wid = tid >> 5;

#pragma unroll
    for (int r = 0; r < 8; r++) ws[tid + 256 * r] = g_w[b * (H_ * D_) + tid + 256 * r];
    if (tid < H_) cs[tid] = g_c[b * H_ + tid];
    __syncthreads();

    const float4* ws4 = (const float4*)ws;
    const float4* emb4 = (const float4*)emb;
    const float4* pos4 = (const float4*)g_Pos;
    float4* xs4 = (float4*)xs;

    int d0 = tid * 2;
    float y00 = 0, y01 = 0, y10 = 0, y11 = 0, y20 = 0, y21 = 0, y30 = 0, y31 = 0;

    for (int sub = 0; sub < 8; sub++) {
        int t0 = chunk * 128 + sub * 16;
        // gather 16 rows (emb[tok] + pos) into shared
#pragma unroll
        for (int r = 0; r < 8; r++) {
            int idx = tid + 256 * r;       // 0..2047
            int row = idx >> 7;
            int c4  = idx & 127;
            int tk  = tok[b * S_ + t0 + row];
            float4 e = emb4[(size_t)tk * 128 + c4];
            float4 p = pos4[(size_t)(t0 + row) * 128 + c4];
            float4 v; v.x = e.x + p.x; v.y = e.y + p.y; v.z = e.z + p.z; v.w = e.w + p.w;
            xs4[row * 128 + c4] = v;
        }
        __syncthreads();

        // alpha: 8 warps x 2 rows
#pragma unroll
        for (int j = 0; j < 2; j++) {
            int tl = wid * 2 + j;
            const float4* xr = (const float4*)&xs[tl][0];
            float s0 = 0.f, s1 = 0.f, s2 = 0.f, s3 = 0.f;
#pragma unroll
            for (int k = 0; k < 4; k++) {
                int f4 = lane + 32 * k;
                float4 xv = xr[f4];
                float4 w0 = ws4[0 * 128 + f4];
                float4 w1 = ws4[1 * 128 + f4];
                float4 w2 = ws4[2 * 128 + f4];
                float4 w3 = ws4[3 * 128 + f4];
                s0 += xv.x * w0.x + xv.y * w0.y + xv.z * w0.z + xv.w * w0.w;
                s1 += xv.x * w1.x + xv.y * w1.y + xv.z * w1.z + xv.w * w1.w;
                s2 += xv.x * w2.x + xv.y * w2.y + xv.z * w2.z + xv.w * w2.w;
                s3 += xv.x * w3.x + xv.y * w3.y + xv.z * w3.z + xv.w * w3.w;
            }
#pragma unroll
            for (int off = 16; off > 0; off >>= 1) {
                s0 += __shfl_xor_sync(0xffffffff, s0, off);
                s1 += __shfl_xor_sync(0xffffffff, s1, off);
                s2 += __shfl_xor_sync(0xffffffff, s2, off);
                s3 += __shfl_xor_sync(0xffffffff, s3, off);
            }
            if (lane == 0) {
                al[sub * 16 + tl][0] = s0 + cs[0];
                al[sub * 16 + tl][1] = s1 + cs[1];
                al[sub * 16 + tl][2] = s2 + cs[2];
                al[sub * 16 + tl][3] = s3 + cs[3];
            }
        }
        __syncthreads();

        // y accumulation from this subtile
#pragma unroll
        for (int t = 0; t < 16; t++) {
            float2 xv = *(const float2*)&xs[t][d0];
            int ta = sub * 16 + t;
            float a0 = al[ta][0], a1 = al[ta][1], a2 = al[ta][2], a3 = al[ta][3];
            y00 += a0 * xv.x; y01 += a0 * xv.y;
            y10 += a1 * xv.x; y11 += a1 * xv.y;
            y20 += a2 * xv.x; y21 += a2 * xv.y;
            y30 += a3 * xv.x; y31 += a3 * xv.y;
        }
        __syncthreads();
    }

    float* yp = g_ypart + ((size_t)(b * NCHUNK_ + chunk)) * (H_ * D_);
    yp[0 * D_ + d0] = y00; yp[0 * D_ + d0 + 1] = y01;
    yp[1 * D_ + d0] = y10; yp[1 * D_ + d0 + 1] = y11;
    yp[2 * D_ + d0] = y20; yp[2 * D_ + d0 + 1] = y21;
    yp[3 * D_ + d0] = y30; yp[3 * D_ + d0 + 1] = y31;

    if (tid < H_) {
        float a = 0.f;
#pragma unroll 8
        for (int t = 0; t < 128; t++) a += al[t][tid];
        g_Apart[(b * NCHUNK_ + chunk) * H_ + tid] = a;
    }
}

// ---------------------------------------------------------------------------
// Reduce y/A partials over chunks
// ---------------------------------------------------------------------------
__global__ __launch_bounds__(256) void reduce_y_kernel() {
    int b = blockIdx.x, tid = threadIdx.x;
#pragma unroll
    for (int r = 0; r < 8; r++) {
        int i = tid + 256 * r;             // 0..2047
        float acc = 0.f;
#pragma unroll
        for (int c = 0; c < NCHUNK_; c++)
            acc += g_ypart[((size_t)(b * NCHUNK_ + c)) * (H_ * D_) + i];
        g_y[(size_t)b * (H_ * D_) + i] = acc;
    }
    if (tid < H_) {
        float a = 0.f;
#pragma unroll
        for (int c = 0; c < NCHUNK_; c++) a += g_Apart[(b * NCHUNK_ + c) * H_ + tid];
        g_A[b * H_ + tid] = a;
    }
}

// ===========================================================================
// Batched skinny GEMMs: C[32, N] = A[32, K] @ W[K, N]   (+init terms)
// Block: 128 threads = 16 col-groups (x4 cols) x 8 batch-groups (x4 b).
// Each block: 64 cols x 256 K-slice. Partials per kb, fixed-order reduce.
// ===========================================================================
#define GEMM_PROLOGUE()                                            \
    __shared__ float As[32][257];                                  \
    int tid = threadIdx.x;                                         \
    int cg = tid & 15, bg = tid >> 4;                              \
    int col = blockIdx.x * 64 + cg * 4;                            \
    int kb = blockIdx.y;                                           \
    (void)col; (void)kb;

#define GEMM_STAGE(EXPR)                                           \
    for (int r = 0; r < 64; r++) {                                 \
        int idx = tid + 128 * r;                                   \
        int bb = idx >> 8;                                         \
        int kk = idx & 255;                                        \
        int kg = kb * 256 + kk;                                    \
        (void)kg;                                                  \
        As[bb][kk] = (EXPR);                                       \
    }                                                              \
    __syncthreads();

#define GEMM_MAIN(WADDR)                                           \
    _Pragma("unroll 4")                                            \
    for (int k = 0; k < 256; k++) {                                \
        int kg = kb * 256 + k;                                     \
        float4 wv = *(const float4*)(WADDR);                       \
        _Pragma("unroll")                                          \
        for (int j = 0; j < 4; j++) {                              \
            float a = As[bg * 4 + j][k];                           \
            acc[j].x += a * wv.x; acc[j].y += a * wv.y;            \
            acc[j].z += a * wv.z; acc[j].w += a * wv.w;            \
        }                                                          \
    }

// ---- F1: heads partials = y @ Wv (+ A*bv in kb==0) ----
__global__ __launch_bounds__(128) void f1_kernel(
    const float* __restrict__ Wp, const float* __restrict__ bp)
{
    GEMM_PROLOGUE();
    int h = col >> 7, f = col & 127;
    GEMM_STAGE(g_y[(size_t)(bb * H_ + h) * D_ + kg]);
    float4 acc[4];
    if (kb == 0) {
        float4 bv = *(const float4*)&bp[h * DH_ + 256 + f];
#pragma unroll
        for (int j = 0; j < 4; j++) {
            float av = g_A[(bg * 4 + j) * H_ + h];
            acc[j].x = av * bv.x; acc[j].y = av * bv.y;
            acc[j].z = av * bv.z; acc[j].w = av * bv.w;
        }
    } else {
#pragma unroll
        for (int j = 0; j < 4; j++) acc[j] = make_float4(0, 0, 0, 0);
    }
    GEMM_MAIN(Wp + ((size_t)h * D_ + kg) * DH_ + 256 + f);
#pragma unroll
    for (int j = 0; j < 4; j++)
        *(float4*)&g_hp[kb][(bg * 4 + j) * D_ + col] = acc[j];
}

// ---- F2: x1 partials = (scale*heads) @ Wo (+ bo + x0 in kb==0) ----
__global__ __launch_bounds__(128) void f2_kernel(
    const float* __restrict__ Wo, const float* __restrict__ bo)
{
    GEMM_PROLOGUE();
    GEMM_STAGE((g_hp[0][bb * D_ + kg] + g_hp[1][bb * D_ + kg]) * 0.03125f);
    float4 acc[4];
    if (kb == 0) {
        float4 bv = *(const float4*)&bo[col];
#pragma unroll
        for (int j = 0; j < 4; j++) {
            float4 xv = *(const float4*)&g_x0[(bg * 4 + j) * D_ + col];
            acc[j].x = bv.x + xv.x; acc[j].y = bv.y + xv.y;
            acc[j].z = bv.z + xv.z; acc[j].w = bv.w + xv.w;
        }
    } else {
#pragma unroll
        for (int j = 0; j < 4; j++) acc[j] = make_float4(0, 0, 0, 0);
    }
    GEMM_MAIN(Wo + (size_t)kg * D_ + col);
#pragma unroll
    for (int j = 0; j < 4; j++)
        *(float4*)&g_x1p[kb][(bg * 4 + j) * D_ + col] = acc[j];
}

// ---- F3: h1 partials = x1n @ W1 (+ b1 in kb==0) ----
__global__ __launch_bounds__(128) void f3_kernel(
    const float* __restrict__ W1, const float* __restrict__ b1)
{
    GEMM_PROLOGUE();
    GEMM_STAGE(g_x1n[bb * D_ + kg]);
    float4 acc[4];
    if (kb == 0) {
        float4 bv = *(const float4*)&b1[col];
#pragma unroll
        for (int j = 0; j < 4; j++) acc[j] = bv;
    } else {
#pragma unroll
        for (int j = 0; j < 4; j++) acc[j] = make_float4(0, 0, 0, 0);
    }
    GEMM_MAIN(W1 + (size_t)kg * FFN_ + col);
#pragma unroll
    for (int j = 0; j < 4; j++)
        *(float4*)&g_h1p[kb][(bg * 4 + j) * FFN_ + col] = acc[j];
}

// ---- F4: x2 partials = relu(h1) @ W2 (+ b2 + x1n in kb==0) ----
__global__ __launch_bounds__(128) void f4_kernel(
    const float* __restrict__ W2, const float* __restrict__ b2)
{
    GEMM_PROLOGUE();
    GEMM_STAGE(fmaxf(g_h1p[0][bb * FFN_ + kg] + g_h1p[1][bb * FFN_ + kg], 0.f));
    float4 acc[4];
    if (kb == 0) {
        float4 bv = *(const float4*)&b2[col];
#pragma unroll
        for (int j = 0; j < 4; j++) {
            float4 xv = *(const float4*)&g_x1n[(bg * 4 + j) * D_ + col];
            acc[j].x = bv.x + xv.x; acc[j].y = bv.y + xv.y;
            acc[j].z = bv.z + xv.z; acc[j].w = bv.w + xv.w;
        }
    } else {
#pragma unroll
        for (int j = 0; j < 4; j++) acc[j] = make_float4(0, 0, 0, 0);
    }
    GEMM_MAIN(W2 + (size_t)kg * D_ + col);
#pragma unroll
    for (int j = 0; j < 4; j++)
        *(float4*)&g_x2p[kb][(bg * 4 + j) * D_ + col] = acc[j];
}

// ---- F5: hid partials = x2 @ Wh (+ bh in kb==0) ----
__global__ __launch_bounds__(128) void f5_kernel(
    const float* __restrict__ Wh, const float* __restrict__ bh)
{
    GEMM_PROLOGUE();
    GEMM_STAGE(g_x2[bb * D_ + kg]);
    float4 acc[4];
    if (kb == 0) {
        float4 bv = *(const float4*)&bh[col];
#pragma unroll
        for (int j = 0; j < 4; j++) acc[j] = bv;
    } else {
#pragma unroll
        for (int j = 0; j < 4; j++) acc[j] = make_float4(0, 0, 0, 0);
    }
    GEMM_MAIN(Wh + (size_t)kg * D_ + col);
#pragma unroll
    for (int j = 0; j < 4; j++)
        *(float4*)&g_hidp[kb][(bg * 4 + j) * D_ + col] = acc[j];
}

// ---------------------------------------------------------------------------
// LayerNorm kernels
// ---------------------------------------------------------------------------
__device__ __forceinline__ float block_sum_512(float v, float* red) {
    int tid = threadIdx.x;
    red[tid] = v;
    __syncthreads();
#pragma unroll
    for (int s = 256; s > 0; s >>= 1) {
        if (tid < s) red[tid] += red[tid + s];
        __syncthreads();
    }
    float r = red[0];
    __syncthreads();
    return r;
}

__global__ __launch_bounds__(512) void ln1_kernel(
    const float* __restrict__ g, const float* __restrict__ bta)
{
    __shared__ float red[512];
    int b = blockIdx.x, tid = threadIdx.x;
    float v = g_x1p[0][b * D_ + tid] + g_x1p[1][b * D_ + tid];
    float mu  = block_sum_512(v, red) * (1.f / D_);
    float dv  = v - mu;
    float var = block_sum_512(dv * dv, red) * (1.f / D_);
    g_x1n[b * D_ + tid] = dv * rsqrtf(var + 1e-3f) * g[tid] + bta[tid];
}

__global__ __launch_bounds__(512) void ln2_kernel(
    const float* __restrict__ g, const float* __restrict__ bta)
{
    __shared__ float red[512];
    int b = blockIdx.x, tid = threadIdx.x;
    float v = 0.f;
#pragma unroll
    for (int c = 0; c < 8; c++) v += g_x2p[c][b * D_ + tid];
    float mu  = block_sum_512(v, red) * (1.f / D_);
    float dv  = v - mu;
    float var = block_sum_512(dv * dv, red) * (1.f / D_);
    g_x2[b * D_ + tid] = dv * rsqrtf(var + 1e-3f) * g[tid] + bta[tid];
}

__global__ __launch_bounds__(512) void logits_kernel(
    const float* __restrict__ Wf, const float* __restrict__ bf,
    float* __restrict__ out, int out_size)
{
    __shared__ float red[512];
    int b = blockIdx.x, tid = threadIdx.x;
    float hid = fmaxf(g_hidp[0][b * D_ + tid] + g_hidp[1][b * D_ + tid], 0.f);
    float s = block_sum_512(hid * Wf[tid], red);
    if (tid == 0) {
        float logit = s + bf[0];
        if (b < out_size)      out[b]      = logit;
        if (B_ + b < out_size) out[B_ + b] = 1.f / (1.f + expf(-logit));
    }
}

// ---------------------------------------------------------------------------
extern "C" void kernel_launch(void* const* d_in, const int* in_sizes, int n_in,
                              void* d_out, int out_size) {
    const int*   inputs = (const int*)  d_in[0];
    const float* emb    = (const float*)d_in[1];
    const float* Wp     = (const float*)d_in[2];
    const float* bp     = (const float*)d_in[3];
    const float* Wo     = (const float*)d_in[4];
    const float* bo     = (const float*)d_in[5];
    const float* ln1g   = (const float*)d_in[6];
    const float* ln1b   = (const float*)d_in[7];
    const float* W1     = (const float*)d_in[8];
    const float* b1     = (const float*)d_in[9];
    const float* W2     = (const float*)d_in[10];
    const float* b2     = (const float*)d_in[11];
    const float* ln2g   = (const float*)d_in[12];
    const float* ln2b   = (const float*)d_in[13];
    const float* Wh     = (const float*)d_in[14];
    const float* bhp    = (const float*)d_in[15];
    const float* Wf     = (const float*)d_in[16];
    const float* bf     = (const float*)d_in[17];
    float* out = (float*)d_out;

    prep_pos_kernel<<<(S_ * D_ + 255) / 256, 256>>>();
    qw_kernel<<<B_, 512>>>(inputs, emb, Wp, bp);
    alpha_y_kernel<<<dim3(NCHUNK_, B_), 256>>>(inputs, emb);
    reduce_y_kernel<<<B_, 256>>>();
    f1_kernel<<<dim3(8, 2), 128>>>(Wp, bp);
    f2_kernel<<<dim3(8, 2), 128>>>(Wo, bo);
    ln1_kernel<<<B_, 512>>>(ln1g, ln1b);
    f3_kernel<<<dim3(32, 2), 128>>>(W1, b1);
    f4_kernel<<<dim3(8, 8), 128>>>(W2, b2);
    ln2_kernel<<<B_, 512>>>(ln2g, ln2b);
    f5_kernel<<<dim3(8, 2), 128>>>(Wh, bhp);
    logits_kernel<<<B_, 512>>>(Wf, bf, out, out_size);
}

// round 4
// speedup vs baseline: 12.1045x; 1.6953x over previous
#include <cuda_runtime.h>
#include <math.h>

namespace {
constexpr int B_   = 32;
constexpr int S_   = 1024;
constexpr int D_   = 512;
constexpr int H_   = 4;
constexpr int DH_  = 384;
constexpr int FFN_ = 2048;
constexpr int NCH_ = 8;     // 128-row chunks for alpha/y
constexpr int NB_  = 148;   // one block per SM — all resident
constexpr int NT_  = 512;
}

// ---------------- static scratch ----------------
__device__ float g_Pos[S_ * D_];                  // 2 MB
__device__ float g_x0[B_ * D_];
__device__ float g_w[B_ * H_ * D_];
__device__ float g_c[B_ * H_];
__device__ float g_ypart[B_ * NCH_ * H_ * D_];    // 2 MB
__device__ float g_Apart[B_ * NCH_ * H_];
__device__ float g_hp[8][B_ * D_];                // F1 partials
__device__ float g_x1p[8][B_ * D_];               // F2 partials
__device__ float g_x1n[B_ * D_];                  // post-LN1
__device__ float g_h1p[8][B_ * FFN_];             // F3 partials
__device__ float g_x2p[32][B_ * D_];              // F4 partials
__device__ float g_x2[B_ * D_];                   // post-LN2
__device__ float g_hidp[8][B_ * D_];              // F5 partials

// ---------------- grid barrier state ----------------
__device__ unsigned g_cnt = 0;
__device__ volatile unsigned g_gen = 0;

__device__ __forceinline__ void grid_bar() {
    __syncthreads();
    if (threadIdx.x == 0) {
        unsigned gen = g_gen;               // read BEFORE arriving
        __threadfence();                    // release our stage's writes
        if (atomicAdd(&g_cnt, 1u) == NB_ - 1u) {
            g_cnt = 0;
            __threadfence();
            g_gen = gen + 1u;
        } else {
            while (g_gen == gen) __nanosleep(64);
        }
        __threadfence();                    // acquire others' writes
    }
    __syncthreads();
}

// ---------------- shared memory union ----------------
struct SA { float xs[16][512]; float ws[2048]; float al[128][4]; float cs[4]; };
struct SG { float As[32][64]; };
struct SQ { float x0s[512]; float q0s[512]; };
struct SR { float red[512]; };

// block reduction over 512 threads
__device__ __forceinline__ float redsum(float v, float* red) {
    int tid = threadIdx.x;
    red[tid] = v;
    __syncthreads();
#pragma unroll
    for (int s = 256; s > 0; s >>= 1) {
        if (tid < s) red[tid] += red[tid + s];
        __syncthreads();
    }
    float r = red[0];
    __syncthreads();
    return r;
}

// Generic batched skinny GEMM stage: C[32, NCT*128] += A[32, NKT*64] @ W
// threads: cg = lane (32 x 4 cols = 128 cols/tile), bg = warp (16 x 2 batches)
#define GEMM_BODY(NCT, NKT, STAGE_EXPR, INIT_STMT, WADDR_EXPR, OUT_STMT)        \
  for (int tt = blk; tt < (NCT) * (NKT); tt += NB_) {                           \
    const int ct = tt / (NKT), kb = tt % (NKT);                                 \
    const int col = ct * 128 + cg * 4;  (void)col;                              \
    _Pragma("unroll")                                                           \
    for (int r = 0; r < 4; r++) {                                               \
      int idx = tid + NT_ * r;                                                  \
      int bb = idx >> 6, kk = idx & 63;                                         \
      int kg = kb * 64 + kk;  (void)kg;                                         \
      sm.g.As[bb][kk] = (STAGE_EXPR);                                           \
    }                                                                           \
    __syncthreads();                                                            \
    float4 acc[2];                                                              \
    INIT_STMT;                                                                  \
    _Pragma("unroll 8")                                                         \
    for (int k = 0; k < 64; k++) {                                              \
      int kg = kb * 64 + k;                                                     \
      float4 wv = *(const float4*)(WADDR_EXPR);                                 \
      _Pragma("unroll")                                                         \
      for (int j = 0; j < 2; j++) {                                             \
        float a = sm.g.As[bg * 2 + j][k];                                       \
        acc[j].x += a * wv.x; acc[j].y += a * wv.y;                             \
        acc[j].z += a * wv.z; acc[j].w += a * wv.w;                             \
      }                                                                         \
    }                                                                           \
    OUT_STMT;                                                                   \
    __syncthreads();                                                            \
  }

#define ACC_ZERO() do {                                                         \
    acc[0] = make_float4(0.f, 0.f, 0.f, 0.f);                                   \
    acc[1] = make_float4(0.f, 0.f, 0.f, 0.f); } while (0)

__global__ __launch_bounds__(NT_, 1) void mega_kernel(
    const int*   __restrict__ tok,  const float* __restrict__ emb,
    const float* __restrict__ Wp,   const float* __restrict__ bp,
    const float* __restrict__ Wo,   const float* __restrict__ bo,
    const float* __restrict__ g1,   const float* __restrict__ bln1,
    const float* __restrict__ W1,   const float* __restrict__ b1,
    const float* __restrict__ W2,   const float* __restrict__ b2,
    const float* __restrict__ g2,   const float* __restrict__ bln2,
    const float* __restrict__ Wh,   const float* __restrict__ bhw,
    const float* __restrict__ Wf,   const float* __restrict__ bf,
    float* __restrict__ out, int out_size)
{
    __shared__ union { SA a; SG g; SQ q; SR r; } sm;
    const int blk = blockIdx.x;
    const int tid = threadIdx.x;
    const int lane = tid & 31, wid = tid >> 5;
    const int cg = lane, bg = wid;

    // ---------------- S0: positional table ----------------
    for (int idx = blk * NT_ + tid; idx < S_ * D_; idx += NB_ * NT_) {
        int t = idx >> 9;
        int i = idx & 511;
        float expn = (float)(2 * (i >> 1)) * (1.0f / (float)D_);
        float ang  = (float)t / powf(10000.0f, expn);
        g_Pos[idx] = (i & 1) ? cosf(ang) : sinf(ang);
    }
    grid_bar();

    // ---------------- S1: x0, q0, w, c  (128 tiles: b*4 + head) ----------------
    if (blk < 128) {
        int b = blk >> 2, qt = blk & 3;
        int t0 = tok[b * S_];
        float v = emb[(size_t)t0 * D_ + tid] + g_Pos[tid];
        sm.q.x0s[tid] = v;
        if (qt == 0) g_x0[b * D_ + tid] = v;
        __syncthreads();

        {   // q0[h,e], one output per thread
            int h = tid >> 7, e = tid & 127;
            const float* wp = Wp + (size_t)h * D_ * DH_ + e;
            float acc = bp[h * DH_ + e];
#pragma unroll 16
            for (int d = 0; d < D_; d++) acc += sm.q.x0s[d] * wp[(size_t)d * DH_];
            sm.q.q0s[tid] = acc;
        }
        __syncthreads();

        if (qt == 0 && tid < H_) {
            float c = 0.f;
            for (int e = 0; e < 128; e++)
                c += sm.q.q0s[tid * 128 + e] * bp[tid * DH_ + 128 + e];
            g_c[b * H_ + tid] = c;
        }
        {   // w for head qt, d = tid
            const float4* wp4 = (const float4*)(Wp + ((size_t)qt * D_ + tid) * DH_ + 128);
            const float4* q4  = (const float4*)(sm.q.q0s + qt * 128);
            float acc = 0.f;
#pragma unroll
            for (int e4 = 0; e4 < 32; e4++) {
                float4 wv = wp4[e4], qv = q4[e4];
                acc += wv.x * qv.x + wv.y * qv.y + wv.z * qv.z + wv.w * qv.w;
            }
            g_w[b * (H_ * D_) + qt * D_ + tid] = acc;
        }
        __syncthreads();
    }
    grid_bar();

    // ---------------- S2: fused gather + alpha + y  (256 tiles) ----------------
    for (int t = blk; t < B_ * NCH_; t += NB_) {
        int b = t & 31, chunk = t >> 5;
        const float4* ws4  = (const float4*)sm.a.ws;
        const float4* emb4 = (const float4*)emb;
        const float4* pos4 = (const float4*)g_Pos;
        float4* xs4 = (float4*)sm.a.xs;

#pragma unroll
        for (int r = 0; r < 4; r++)
            sm.a.ws[tid + NT_ * r] = g_w[b * (H_ * D_) + tid + NT_ * r];
        if (tid < H_) sm.a.cs[tid] = g_c[b * H_ + tid];
        __syncthreads();

        float y0 = 0.f, y1 = 0.f, y2 = 0.f, y3 = 0.f;   // col = tid, 4 heads

        for (int sub = 0; sub < 8; sub++) {
            int r0 = chunk * 128 + sub * 16;
            // gather 16 rows of emb[tok]+pos into shared
#pragma unroll
            for (int r = 0; r < 4; r++) {
                int idx = tid + NT_ * r;         // 0..2047 float4 slots
                int row = idx >> 7, c4 = idx & 127;
                int tk  = tok[b * S_ + r0 + row];
                float4 e = emb4[(size_t)tk * 128 + c4];
                float4 p = pos4[(size_t)(r0 + row) * 128 + c4];
                float4 vv;
                vv.x = e.x + p.x; vv.y = e.y + p.y; vv.z = e.z + p.z; vv.w = e.w + p.w;
                xs4[row * 128 + c4] = vv;
            }
            __syncthreads();

            // alpha: 16 warps, one row each
            {
                const float4* xr = (const float4*)&sm.a.xs[wid][0];
                float s0 = 0.f, s1 = 0.f, s2 = 0.f, s3 = 0.f;
#pragma unroll
                for (int k = 0; k < 4; k++) {
                    int f4 = lane + 32 * k;
                    float4 xv = xr[f4];
                    float4 w0 = ws4[0 * 128 + f4];
                    float4 w1 = ws4[1 * 128 + f4];
                    float4 w2 = ws4[2 * 128 + f4];
                    float4 w3 = ws4[3 * 128 + f4];
                    s0 += xv.x * w0.x + xv.y * w0.y + xv.z * w0.z + xv.w * w0.w;
                    s1 += xv.x * w1.x + xv.y * w1.y + xv.z * w1.z + xv.w * w1.w;
                    s2 += xv.x * w2.x + xv.y * w2.y + xv.z * w2.z + xv.w * w2.w;
                    s3 += xv.x * w3.x + xv.y * w3.y + xv.z * w3.z + xv.w * w3.w;
                }
#pragma unroll
                for (int off = 16; off > 0; off >>= 1) {
                    s0 += __shfl_xor_sync(0xffffffff, s0, off);
                    s1 += __shfl_xor_sync(0xffffffff, s1, off);
                    s2 += __shfl_xor_sync(0xffffffff, s2, off);
                    s3 += __shfl_xor_sync(0xffffffff, s3, off);
                }
                if (lane == 0) {
                    sm.a.al[sub * 16 + wid][0] = s0 + sm.a.cs[0];
                    sm.a.al[sub * 16 + wid][1] = s1 + sm.a.cs[1];
                    sm.a.al[sub * 16 + wid][2] = s2 + sm.a.cs[2];
                    sm.a.al[sub * 16 + wid][3] = s3 + sm.a.cs[3];
                }
            }
            __syncthreads();

            // y accumulation
#pragma unroll
            for (int tt = 0; tt < 16; tt++) {
                float xv = sm.a.xs[tt][tid];
                int ta = sub * 16 + tt;
                y0 += sm.a.al[ta][0] * xv;
                y1 += sm.a.al[ta][1] * xv;
                y2 += sm.a.al[ta][2] * xv;
                y3 += sm.a.al[ta][3] * xv;
            }
            __syncthreads();
        }

        float* yp = g_ypart + ((size_t)(b * NCH_ + chunk)) * (H_ * D_);
        yp[0 * D_ + tid] = y0;
        yp[1 * D_ + tid] = y1;
        yp[2 * D_ + tid] = y2;
        yp[3 * D_ + tid] = y3;
        if (tid < H_) {
            float a = 0.f;
#pragma unroll 8
            for (int r = 0; r < 128; r++) a += sm.a.al[r][tid];
            g_Apart[(b * NCH_ + chunk) * H_ + tid] = a;
        }
        __syncthreads();
    }
    grid_bar();

    // ---------------- F1: heads = y @ Wv + A*bv   (4 x 8 tiles) ----------------
    {
        GEMM_BODY(4, 8,
            /*stage*/ ({
                float s = 0.f;
                _Pragma("unroll")
                for (int c = 0; c < NCH_; c++)
                    s += g_ypart[((size_t)(bb * NCH_ + c)) * (H_ * D_) + ct * D_ + kg];
                s; }),
            /*init*/ do {
                if (kb == 0) {
                    float4 bv = *(const float4*)&bp[ct * DH_ + 256 + cg * 4];
                    _Pragma("unroll")
                    for (int j = 0; j < 2; j++) {
                        int bj = bg * 2 + j;
                        float av = 0.f;
                        _Pragma("unroll")
                        for (int c = 0; c < NCH_; c++) av += g_Apart[(bj * NCH_ + c) * H_ + ct];
                        acc[j].x = av * bv.x; acc[j].y = av * bv.y;
                        acc[j].z = av * bv.z; acc[j].w = av * bv.w;
                    }
                } else ACC_ZERO();
            } while (0),
            /*W*/ (Wp + ((size_t)ct * D_ + kg) * DH_ + 256 + cg * 4),
            /*out*/ do {
                _Pragma("unroll")
                for (int j = 0; j < 2; j++)
                    *(float4*)&g_hp[kb][(bg * 2 + j) * D_ + col] = acc[j];
            } while (0));
    }
    grid_bar();

    // ---------------- F2: x1 = scale*heads @ Wo + bo + x0  (4 x 8) ----------------
    {
        GEMM_BODY(4, 8,
            /*stage*/ ({
                float s = 0.f;
                _Pragma("unroll")
                for (int p = 0; p < 8; p++) s += g_hp[p][bb * D_ + kg];
                s * 0.03125f; }),
            /*init*/ do {
                if (kb == 0) {
                    float4 bv = *(const float4*)&bo[col];
                    _Pragma("unroll")
                    for (int j = 0; j < 2; j++) {
                        float4 xv = *(const float4*)&g_x0[(bg * 2 + j) * D_ + col];
                        acc[j].x = bv.x + xv.x; acc[j].y = bv.y + xv.y;
                        acc[j].z = bv.z + xv.z; acc[j].w = bv.w + xv.w;
                    }
                } else ACC_ZERO();
            } while (0),
            /*W*/ (Wo + (size_t)kg * D_ + col),
            /*out*/ do {
                _Pragma("unroll")
                for (int j = 0; j < 2; j++)
                    *(float4*)&g_x1p[kb][(bg * 2 + j) * D_ + col] = acc[j];
            } while (0));
    }
    grid_bar();

    // ---------------- LN1 (32 blocks) ----------------
    if (blk < B_) {
        int b = blk;
        float v = 0.f;
#pragma unroll
        for (int p = 0; p < 8; p++) v += g_x1p[p][b * D_ + tid];
        float mu  = redsum(v, sm.r.red) * (1.f / D_);
        float dv  = v - mu;
        float var = redsum(dv * dv, sm.r.red) * (1.f / D_);
        g_x1n[b * D_ + tid] = dv * rsqrtf(var + 1e-3f) * g1[tid] + bln1[tid];
    }
    grid_bar();

    // ---------------- F3: h1 = x1n @ W1 + b1   (16 x 8 tiles) ----------------
    {
        GEMM_BODY(16, 8,
            /*stage*/ (g_x1n[bb * D_ + kg]),
            /*init*/ do {
                if (kb == 0) {
                    float4 bv = *(const float4*)&b1[col];
                    acc[0] = bv; acc[1] = bv;
                } else ACC_ZERO();
            } while (0),
            /*W*/ (W1 + (size_t)kg * FFN_ + col),
            /*out*/ do {
                _Pragma("unroll")
                for (int j = 0; j < 2; j++)
                    *(float4*)&g_h1p[kb][(bg * 2 + j) * FFN_ + col] = acc[j];
            } while (0));
    }
    grid_bar();

    // ---------------- F4: x2 = relu(h1) @ W2 + b2 + x1n  (4 x 32 tiles) ----------------
    {
        GEMM_BODY(4, 32,
            /*stage*/ ({
                float s = 0.f;
                _Pragma("unroll")
                for (int p = 0; p < 8; p++) s += g_h1p[p][bb * FFN_ + kg];
                fmaxf(s, 0.f); }),
            /*init*/ do {
                if (kb == 0) {
                    float4 bv = *(const float4*)&b2[col];
                    _Pragma("unroll")
                    for (int j = 0; j < 2; j++) {
                        float4 xv = *(const float4*)&g_x1n[(bg * 2 + j) * D_ + col];
                        acc[j].x = bv.x + xv.x; acc[j].y = bv.y + xv.y;
                        acc[j].z = bv.z + xv.z; acc[j].w = bv.w + xv.w;
                    }
                } else ACC_ZERO();
            } while (0),
            /*W*/ (W2 + (size_t)kg * D_ + col),
            /*out*/ do {
                _Pragma("unroll")
                for (int j = 0; j < 2; j++)
                    *(float4*)&g_x2p[kb][(bg * 2 + j) * D_ + col] = acc[j];
            } while (0));
    }
    grid_bar();

    // ---------------- LN2 (32 blocks) ----------------
    if (blk < B_) {
        int b = blk;
        float v = 0.f;
#pragma unroll
        for (int p = 0; p < 32; p++) v += g_x2p[p][b * D_ + tid];
        float mu  = redsum(v, sm.r.red) * (1.f / D_);
        float dv  = v - mu;
        float var = redsum(dv * dv, sm.r.red) * (1.f / D_);
        g_x2[b * D_ + tid] = dv * rsqrtf(var + 1e-3f) * g2[tid] + bln2[tid];
    }
    grid_bar();

    // ---------------- F5: hid = x2 @ Wh + bh   (4 x 8 tiles) ----------------
    {
        GEMM_BODY(4, 8,
            /*stage*/ (g_x2[bb * D_ + kg]),
            /*init*/ do {
                if (kb == 0) {
                    float4 bv = *(const float4*)&bhw[col];
                    acc[0] = bv; acc[1] = bv;
                } else ACC_ZERO();
            } while (0),
            /*W*/ (Wh + (size_t)kg * D_ + col),
            /*out*/ do {
                _Pragma("unroll")
                for (int j = 0; j < 2; j++)
                    *(float4*)&g_hidp[kb][(bg * 2 + j) * D_ + col] = acc[j];
            } while (0));
    }
    grid_bar();

    // ---------------- logits (32 blocks) ----------------
    if (blk < B_) {
        int b = blk;
        float v = 0.f;
#pragma unroll
        for (int p = 0; p < 8; p++) v += g_hidp[p][b * D_ + tid];
        float hid = fmaxf(v, 0.f);
        float s = redsum(hid * Wf[tid], sm.r.red);
        if (tid == 0) {
            float logit = s + bf[0];
            if (b < out_size)      out[b]      = logit;
            if (B_ + b < out_size) out[B_ + b] = 1.f / (1.f + expf(-logit));
        }
    }
}

// ---------------------------------------------------------------------------
extern "C" void kernel_launch(void* const* d_in, const int* in_sizes, int n_in,
                              void* d_out, int out_size) {
    const int*   inputs = (const int*)  d_in[0];
    const float* emb    = (const float*)d_in[1];
    const float* Wp     = (const float*)d_in[2];
    const float* bp     = (const float*)d_in[3];
    const float* Wo     = (const float*)d_in[4];
    const float* bo     = (const float*)d_in[5];
    const float* ln1g   = (const float*)d_in[6];
    const float* ln1b   = (const float*)d_in[7];
    const float* W1     = (const float*)d_in[8];
    const float* b1     = (const float*)d_in[9];
    const float* W2     = (const float*)d_in[10];
    const float* b2     = (const float*)d_in[11];
    const float* ln2g   = (const float*)d_in[12];
    const float* ln2b   = (const float*)d_in[13];
    const float* Wh     = (const float*)d_in[14];
    const float* bhp    = (const float*)d_in[15];
    const float* Wf     = (const float*)d_in[16];
    const float* bf     = (const float*)d_in[17];
    float* out = (float*)d_out;

    mega_kernel<<<NB_, NT_>>>(inputs, emb, Wp, bp, Wo, bo, ln1g, ln1b,
                              W1, b1, W2, b2, ln2g, ln2b, Wh, bhp, Wf, bf,
                              out, out_size);
}